// round 5
// baseline (speedup 1.0000x reference)
#include <cuda_runtime.h>
#include <math.h>

#define HH 256
#define WW 512
#define CC 16
#define ND 32
#define HW (HH * WW)
#define NDHW (ND * HW)
#define BASELINE_V 0.24f
#define WTILE 64
#define MAX_ROWS 48

// Horizontally pre-interpolated y, 4 channel-chunk planes:
// g_Z[chunk*HW + r*WW + w] = {4 ch} of (1-wx)*vx0*y[r][xc0] + wx*vx1*y[r][xc1]
__device__ float4 g_Z[4 * HW];

// ---------------- Kernel 1: horizontal interp + transpose ----------------
__global__ __launch_bounds__(256) void hinterp_kernel(const float* __restrict__ y)
{
    int p = blockIdx.x * 256 + threadIdx.x;   // HW threads
    int w = p & (WW - 1);
    int rbase = p - w;

    float ix = (float)w * ((float)WW / ((float)WW - 1.0f)) - 0.5f;
    float fx0 = floorf(ix);
    float wx  = ix - fx0;
    int xi0 = (int)fx0, xi1 = xi0 + 1;
    float w0x = (xi0 >= 0 && xi0 < WW) ? (1.0f - wx) : 0.0f;
    float w1x = (xi1 >= 0 && xi1 < WW) ? wx : 0.0f;
    int xc0 = min(max(xi0, 0), WW - 1);
    int xc1 = min(max(xi1, 0), WW - 1);

    #pragma unroll
    for (int chunk = 0; chunk < 4; chunk++) {
        float v[4];
        #pragma unroll
        for (int c = 0; c < 4; c++) {
            const float* yc = y + (chunk * 4 + c) * HW + rbase;
            v[c] = w0x * __ldg(yc + xc0) + w1x * __ldg(yc + xc1);
        }
        g_Z[chunk * HW + p] = make_float4(v[0], v[1], v[2], v[3]);
    }
}

// vertical sample position for a given h (theta precomputed) and depth
__device__ __forceinline__ float iy_of(float dep, float st, float ct, float theta, float h)
{
    float dvr = atanf((dep * st + BASELINE_V) / (dep * ct)) - theta;
    float dv  = dvr * ((float)HH / 3.14159265358979323846f);
    float ypx = isfinite(dv) ? (h + dv) : 0.0f;
    return ypx * ((float)HH / ((float)HH - 1.0f)) - 0.5f;
}

// ---------------- Kernel 2: smem-staged fused kernel ----------------
// grid.x = 4 chunks (fastest) * 8 wtiles, grid.y = HH.
// Block: 256 threads = 64 w-lanes x 4 d-groups; thread loops 8 disparities.
__global__ __launch_bounds__(256, 4) void fused_cv_kernel(const float* __restrict__ x,
                                                          const float* __restrict__ depth,
                                                          float* __restrict__ out)
{
    __shared__ float4 s_Z[MAX_ROWS * WTILE];   // 48 KB

    int chunk = blockIdx.x & 3;
    int wt    = blockIdx.x >> 2;
    int h     = blockIdx.y;
    int wl    = threadIdx.x & (WTILE - 1);     // local w
    int dg    = threadIdx.x >> 6;              // d-group 0..3
    int wbase = wt * WTILE;
    int w     = wbase + wl;
    int c0    = chunk * 4;

    const float PI = 3.14159265358979323846f;
    float hf = (float)h;
    float theta = (hf + 0.5f) * (PI / (float)HH) - 0.5f * PI;
    float st, ct;
    sincosf(theta, &st, &ct);

    // row range needed by ALL depths at this h: iy monotone decreasing in depth
    float iy_min = iy_of(8.0f, st, ct, theta, hf);
    float iy_max = iy_of(0.5f, st, ct, theta, hf);
    int r_lo = min(max((int)floorf(iy_min) - 1, 0), HH - 1);
    int r_hi = min(max((int)floorf(iy_max) + 2, 0), HH - 1);
    int nrows = r_hi - r_lo + 1;               // <= 44 by construction

    // cooperative fill of Z rows into smem
    const float4* __restrict__ plane = g_Z + (size_t)chunk * HW;
    for (int i = threadIdx.x; i < nrows * WTILE; i += 256) {
        int row = i >> 6;
        int col = i & (WTILE - 1);
        s_Z[i] = __ldg(plane + (r_lo + row) * WW + wbase + col);
    }

    // x values (d-invariant)
    int hw = h * WW + w;
    float x0v = __ldg(x + (c0 + 0) * HW + hw);
    float x1v = __ldg(x + (c0 + 1) * HW + hw);
    float x2v = __ldg(x + (c0 + 2) * HW + hw);
    float x3v = __ldg(x + (c0 + 3) * HW + hw);

    __syncthreads();

    const float* dp = depth + hw;
    float* ob_x = out + (size_t)c0 * NDHW + hw;
    float* ob_y = out + (size_t)(CC + c0) * NDHW + hw;

    int d0 = dg * 8;
    #pragma unroll 2
    for (int k = 0; k < 8; k++) {
        int d = d0 + k;
        float dep = __ldg(dp + d * HW);
        float iy  = iy_of(dep, st, ct, theta, hf);

        float fy0 = floorf(iy);
        float wy  = iy - fy0;
        int yi0 = (int)fy0, yi1 = yi0 + 1;
        float wA = (yi0 >= 0 && yi0 < HH) ? (1.0f - wy) : 0.0f;
        float wB = (yi1 >= 0 && yi1 < HH) ? wy : 0.0f;
        int yc0 = min(max(yi0, 0), HH - 1);
        int yc1 = min(max(yi1, 0), HH - 1);

        // defensive clamp into staged range (bounds are exact modulo ulps)
        int ry0 = min(max(yc0 - r_lo, 0), nrows - 1);
        int ry1 = min(max(yc1 - r_lo, 0), nrows - 1);

        float4 a = s_Z[ry0 * WTILE + wl];
        float4 b = s_Z[ry1 * WTILE + wl];

        float r0 = fmaf(wA, a.x, wB * b.x);
        float r1 = fmaf(wA, a.y, wB * b.y);
        float r2 = fmaf(wA, a.z, wB * b.z);
        float r3 = fmaf(wA, a.w, wB * b.w);

        int od = d * HW;
        __stcs(ob_y + od + 0 * NDHW, r0);
        __stcs(ob_y + od + 1 * NDHW, r1);
        __stcs(ob_y + od + 2 * NDHW, r2);
        __stcs(ob_y + od + 3 * NDHW, r3);

        __stcs(ob_x + od + 0 * NDHW, x0v);
        __stcs(ob_x + od + 1 * NDHW, x1v);
        __stcs(ob_x + od + 2 * NDHW, x2v);
        __stcs(ob_x + od + 3 * NDHW, x3v);
    }
}

extern "C" void kernel_launch(void* const* d_in, const int* in_sizes, int n_in,
                              void* d_out, int out_size) {
    const float* x     = (const float*)d_in[0];
    const float* y     = (const float*)d_in[1];
    const float* depth = (const float*)d_in[2];
    float* out = (float*)d_out;

    hinterp_kernel<<<HW / 256, 256>>>(y);
    dim3 grid(4 * (WW / WTILE), HH);   // chunk fastest -> depth rows shared in L2
    fused_cv_kernel<<<grid, 256>>>(x, depth, out);
}

// round 6
// speedup vs baseline: 1.0196x; 1.0196x over previous
#include <cuda_runtime.h>
#include <math.h>

#define HH 256
#define WW 512
#define CC 16
#define ND 32
#define HW (HH * WW)
#define NDHW (ND * HW)
#define BASELINE_V 0.24f
#define WTILE 64
#define SROW 67          // padded smem row stride in float4 (67*4 words %32 = 12)
#define MAX_ROWS 48

// Horizontally pre-interpolated y, 4 channel-chunk planes
__device__ float4 g_Z[4 * HW];
// Precomputed vertical sample position per (d,h,w)
__device__ float g_iy[NDHW];

__device__ __forceinline__ float iy_of(float dep, float st, float ct, float theta, float h)
{
    float dvr = atanf((dep * st + BASELINE_V) / (dep * ct)) - theta;
    float dv  = dvr * ((float)HH / 3.14159265358979323846f);
    float ypx = isfinite(dv) ? (h + dv) : 0.0f;
    return ypx * ((float)HH / ((float)HH - 1.0f)) - 0.5f;
}

// ---------------- Kernel 1: horizontal interp + transpose ----------------
__global__ __launch_bounds__(256) void hinterp_kernel(const float* __restrict__ y)
{
    int p = blockIdx.x * 256 + threadIdx.x;   // HW threads
    int w = p & (WW - 1);
    int rbase = p - w;

    float ix = (float)w * ((float)WW / ((float)WW - 1.0f)) - 0.5f;
    float fx0 = floorf(ix);
    float wx  = ix - fx0;
    int xi0 = (int)fx0, xi1 = xi0 + 1;
    float w0x = (xi0 >= 0 && xi0 < WW) ? (1.0f - wx) : 0.0f;
    float w1x = (xi1 >= 0 && xi1 < WW) ? wx : 0.0f;
    int xc0 = min(max(xi0, 0), WW - 1);
    int xc1 = min(max(xi1, 0), WW - 1);

    #pragma unroll
    for (int chunk = 0; chunk < 4; chunk++) {
        float v[4];
        #pragma unroll
        for (int c = 0; c < 4; c++) {
            const float* yc = y + (chunk * 4 + c) * HW + rbase;
            v[c] = w0x * __ldg(yc + xc0) + w1x * __ldg(yc + xc1);
        }
        g_Z[chunk * HW + p] = make_float4(v[0], v[1], v[2], v[3]);
    }
}

// ---------------- Kernel 2: precompute iy per (d,h,w) ----------------
__global__ __launch_bounds__(256) void iy_kernel(const float* __restrict__ depth)
{
    int idx = blockIdx.x * 256 + threadIdx.x;   // NDHW/4 threads
    int h = (idx >> 7) & (HH - 1);

    const float PI = 3.14159265358979323846f;
    float hf = (float)h;
    float theta = (hf + 0.5f) * (PI / (float)HH) - 0.5f * PI;
    float st, ct;
    sincosf(theta, &st, &ct);

    float4 dep = ((const float4*)depth)[idx];
    float4 r;
    r.x = iy_of(dep.x, st, ct, theta, hf);
    r.y = iy_of(dep.y, st, ct, theta, hf);
    r.z = iy_of(dep.z, st, ct, theta, hf);
    r.w = iy_of(dep.w, st, ct, theta, hf);
    ((float4*)g_iy)[idx] = r;
}

// ---------------- Kernel 3: smem-staged, vector-store fused kernel ----------------
// grid (4 chunks * 8 wtiles, HH). Block 256: wg=tid&15 (4 w each), dg=tid>>4 (2 d each).
__global__ __launch_bounds__(256, 4) void fused_cv_kernel(const float* __restrict__ x,
                                                          float* __restrict__ out)
{
    __shared__ float4 s_Z[MAX_ROWS * SROW];   // ~50.2 KB

    int chunk = blockIdx.x & 3;
    int wt    = blockIdx.x >> 2;
    int h     = blockIdx.y;
    int wg    = threadIdx.x & 15;
    int dg    = threadIdx.x >> 4;              // 0..15
    int wbase = wt * WTILE;
    int w0    = wbase + wg * 4;
    int c0    = chunk * 4;

    const float PI = 3.14159265358979323846f;
    float hf = (float)h;
    float theta = (hf + 0.5f) * (PI / (float)HH) - 0.5f * PI;
    float st, ct;
    sincosf(theta, &st, &ct);

    // row range for all depths at this h (iy monotone decreasing in depth)
    float iy_min = iy_of(8.0f, st, ct, theta, hf);
    float iy_max = iy_of(0.5f, st, ct, theta, hf);
    int r_lo = min(max((int)floorf(iy_min) - 1, 0), HH - 1);
    int r_hi = min(max((int)floorf(iy_max) + 2, 0), HH - 1);
    int nrows = r_hi - r_lo + 1;               // <= 44

    const float4* __restrict__ plane = g_Z + (size_t)chunk * HW;
    for (int i = threadIdx.x; i < nrows * WTILE; i += 256) {
        int row = i >> 6;
        int col = i & (WTILE - 1);
        s_Z[row * SROW + col] = __ldg(plane + (r_lo + row) * WW + wbase + col);
    }

    // x values: 4 channels x 4 w (d-invariant), vector loads
    int hw0 = h * WW + w0;
    float4 xv0 = *(const float4*)(x + (size_t)(c0 + 0) * HW + hw0);
    float4 xv1 = *(const float4*)(x + (size_t)(c0 + 1) * HW + hw0);
    float4 xv2 = *(const float4*)(x + (size_t)(c0 + 2) * HW + hw0);
    float4 xv3 = *(const float4*)(x + (size_t)(c0 + 3) * HW + hw0);

    __syncthreads();

    #pragma unroll
    for (int k = 0; k < 2; k++) {
        int d = dg * 2 + k;
        float4 iy4 = *(const float4*)(g_iy + (size_t)d * HW + hw0);

        float oc[4][4];
        #pragma unroll
        for (int j = 0; j < 4; j++) {
            float iy = (j == 0) ? iy4.x : (j == 1) ? iy4.y : (j == 2) ? iy4.z : iy4.w;
            float fy0 = floorf(iy);
            float wy  = iy - fy0;
            int yi0 = (int)fy0, yi1 = yi0 + 1;
            float wA = (yi0 >= 0 && yi0 < HH) ? (1.0f - wy) : 0.0f;
            float wB = (yi1 >= 0 && yi1 < HH) ? wy : 0.0f;
            int yc0 = min(max(yi0, 0), HH - 1);
            int yc1 = min(max(yi1, 0), HH - 1);
            int ry0 = min(max(yc0 - r_lo, 0), nrows - 1);
            int ry1 = min(max(yc1 - r_lo, 0), nrows - 1);

            float4 a = s_Z[ry0 * SROW + wg * 4 + j];
            float4 b = s_Z[ry1 * SROW + wg * 4 + j];
            oc[0][j] = fmaf(wA, a.x, wB * b.x);
            oc[1][j] = fmaf(wA, a.y, wB * b.y);
            oc[2][j] = fmaf(wA, a.z, wB * b.z);
            oc[3][j] = fmaf(wA, a.w, wB * b.w);
        }

        size_t base = (size_t)d * HW + hw0;
        float* oy = out + (size_t)(CC + c0) * NDHW + base;
        float* ox = out + (size_t)c0 * NDHW + base;
        __stcs((float4*)(oy + 0 * (size_t)NDHW), make_float4(oc[0][0], oc[0][1], oc[0][2], oc[0][3]));
        __stcs((float4*)(oy + 1 * (size_t)NDHW), make_float4(oc[1][0], oc[1][1], oc[1][2], oc[1][3]));
        __stcs((float4*)(oy + 2 * (size_t)NDHW), make_float4(oc[2][0], oc[2][1], oc[2][2], oc[2][3]));
        __stcs((float4*)(oy + 3 * (size_t)NDHW), make_float4(oc[3][0], oc[3][1], oc[3][2], oc[3][3]));
        __stcs((float4*)(ox + 0 * (size_t)NDHW), xv0);
        __stcs((float4*)(ox + 1 * (size_t)NDHW), xv1);
        __stcs((float4*)(ox + 2 * (size_t)NDHW), xv2);
        __stcs((float4*)(ox + 3 * (size_t)NDHW), xv3);
    }
}

extern "C" void kernel_launch(void* const* d_in, const int* in_sizes, int n_in,
                              void* d_out, int out_size) {
    const float* x     = (const float*)d_in[0];
    const float* y     = (const float*)d_in[1];
    const float* depth = (const float*)d_in[2];
    float* out = (float*)d_out;

    hinterp_kernel<<<HW / 256, 256>>>(y);
    iy_kernel<<<(NDHW / 4) / 256, 256>>>(depth);
    dim3 grid(4 * (WW / WTILE), HH);
    fused_cv_kernel<<<grid, 256>>>(x, out);
}